// round 12
// baseline (speedup 1.0000x reference)
#include <cuda_runtime.h>
#include <cuda_bf16.h>
#include <math.h>
#include <stdint.h>

// ---------------- problem constants ----------------
#define NGRAPH 128
#define NPER   20
#define NNODES 2560          // 128*20
#define EPG    380           // 20*19
#define NEDGE  48640         // 128*380
#define DIM    64
#define H1DIM  128
#define KK     8192          // H1DIM*DIM
#define KSPLIT 32            // k_agg K-splits (each CTA covers 256 k)

// ---------------- packed f32x2 helpers (sm_100+) ----------------
#define FMA2(acc, a, b) asm("fma.rn.f32x2 %0, %1, %2, %0;" : "+l"(acc) : "l"(a), "l"(b))
#define PACK2(out, f)   asm("mov.b64 %0, {%1, %1};" : "=l"(out) : "f"(f))
#define PACK2U(out, u)  asm("mov.b64 %0, {%1, %1};" : "=l"(out) : "r"(u))
#define PACK2UU(out, a, b) asm("mov.b64 %0, {%1, %2};" : "=l"(out) : "r"(a), "r"(b))
#define UNPK2(lo, hi, p) asm("mov.b64 {%0, %1}, %2;" : "=f"(lo), "=f"(hi) : "l"(p))
#define CVTB2(out, lo, hi) asm("cvt.rn.bf16x2.f32 %0, %1, %2;" : "=r"(out) : "f"(hi), "f"(lo))

// ---------------- scratch (static device globals; no allocation) ----------------
__device__ unsigned short g_h1b[NEDGE * H1DIM];   // 12.5 MB bf16 edge MLP hidden
__device__ unsigned short g_Pb[NNODES * KK];      // 42 MB bf16 outer-product accumulators
__device__ float g_part[KSPLIT * NNODES * DIM];   // 21 MB split-K partials
__device__ float g_out[NNODES * DIM];
__device__ float g_h  [NNODES * DIM];
__device__ float g_wihT[64 * 192];                // GRU weights transposed [i][j]
__device__ float g_whhT[64 * 192];

__device__ __forceinline__ float sigf(float x) { return 1.0f / (1.0f + expf(-x)); }

// ---------------- out = relu(x @ lin0_w + b); h = out ----------------
__global__ void k_lin0(const float* __restrict__ x, const float* __restrict__ w,
                       const float* __restrict__ b) {
    int idx = blockIdx.x * 256 + threadIdx.x;
    if (idx >= NNODES * DIM) return;
    int n = idx >> 6, o = idx & 63;
    const float* xr = x + n * 11;
    float acc = b[o];
#pragma unroll
    for (int f = 0; f < 11; f++) acc = fmaf(xr[f], w[f * 64 + o], acc);
    acc = fmaxf(acc, 0.0f);
    g_out[idx] = acc;
    g_h[idx]   = acc;
}

// ---------------- h1 = relu(edge_attr @ nn1_w + nn1_b) -> bf16 ----------------
__global__ void k_edge(const float* __restrict__ ea, const float* __restrict__ w,
                       const float* __restrict__ b) {
    int idx = blockIdx.x * 256 + threadIdx.x;
    if (idx >= NEDGE * H1DIM) return;
    int e = idx >> 7, k = idx & 127;
    const float* er = ea + e * 5;
    float acc = b[k];
#pragma unroll
    for (int f = 0; f < 5; f++) acc = fmaf(er[f], w[f * 128 + k], acc);
    acc = fmaxf(acc, 0.0f);
    g_h1b[idx] = __bfloat16_as_ushort(__float2bfloat16(acc));
}

// ---------------- transpose GRU weights (once) ----------------
__global__ void k_prepw(const float* __restrict__ wih, const float* __restrict__ whh) {
    int idx = blockIdx.x * 256 + threadIdx.x;
    if (idx >= 64 * 192) return;
    int i = idx / 192, j = idx % 192;
    g_wihT[idx] = wih[j * 64 + i];
    g_whhT[idx] = whh[j * 64 + i];
}

// ---------------- P[d] = sum_s h1[s->d] (outer) out[s] -> bf16 ----------------
// 128 threads; thread tile 8 k x 8 i; all operands straight from global
// (x rows L2-resident, reused by all 20 dst CTAs of the graph; no smem, no syncs)
__global__ void __launch_bounds__(128) k_p() {
    int n = blockIdx.x;
    int g = n / NPER, d = n % NPER;
    int t = threadIdx.x;
    int kg = t >> 3, ig = t & 7;        // k = kg*8..+7, i = ig*8..+7
    const float* xbase = g_out + (size_t)g * NPER * 64 + (ig << 3);
    const unsigned short* hbase = g_h1b + (size_t)g * EPG * 128 + (kg << 3);

    unsigned long long acc[8][4];       // [k][i-pair] f32x2
#pragma unroll
    for (int k = 0; k < 8; k++)
#pragma unroll
        for (int c = 0; c < 4; c++) acc[k][c] = 0ULL;

    for (int sI = 0; sI < 19; sI++) {
        int s = sI + (sI >= d);
        int j = (d < s) ? d : d - 1;
        ulonglong2 xa = *(const ulonglong2*)(xbase + s * 64);
        ulonglong2 xb = *(const ulonglong2*)(xbase + s * 64 + 4);
        uint4 hq = *(const uint4*)(hbase + (size_t)(s * 19 + j) * 128);
        unsigned hw[4] = {hq.x, hq.y, hq.z, hq.w};
#pragma unroll
        for (int p = 0; p < 4; p++) {
            unsigned long long plo, phi;
            PACK2U(plo, hw[p] << 16);
            PACK2U(phi, hw[p] & 0xFFFF0000u);
            int k0 = p << 1, k1 = k0 + 1;
            FMA2(acc[k0][0], plo, xa.x); FMA2(acc[k0][1], plo, xa.y);
            FMA2(acc[k0][2], plo, xb.x); FMA2(acc[k0][3], plo, xb.y);
            FMA2(acc[k1][0], phi, xa.x); FMA2(acc[k1][1], phi, xa.y);
            FMA2(acc[k1][2], phi, xb.x); FMA2(acc[k1][3], phi, xb.y);
        }
    }

    unsigned short* pd = g_Pb + (size_t)n * KK + (ig << 3);
#pragma unroll
    for (int k = 0; k < 8; k++) {
        unsigned o0, o1, o2, o3;
        float lo, hi;
        UNPK2(lo, hi, acc[k][0]); CVTB2(o0, lo, hi);
        UNPK2(lo, hi, acc[k][1]); CVTB2(o1, lo, hi);
        UNPK2(lo, hi, acc[k][2]); CVTB2(o2, lo, hi);
        UNPK2(lo, hi, acc[k][3]); CVTB2(o3, lo, hi);
        *(uint4*)(pd + ((kg << 3) + k) * 64) = make_uint4(o0, o1, o2, o3);
    }
}

// ---------------- k_agg: partial[ks] = Pb[128-row tile] @ T over 256-k slice ----------------
__global__ void __launch_bounds__(128, 4) k_agg(const float* __restrict__ nn2w) {
    __shared__ unsigned Tsu[32 * 32];   // 4 KB: [k][col-pair] bf16x2
    int bx = blockIdx.x;
    int tile = bx >> 5, ks = bx & 31;
    int n0 = tile * 128;
    int kbase = ks * 256;
    int t = threadIdx.x;
    int tx = t & 7, ry = t >> 3;        // cols tx*8..+7, rows ry*8..+7
    int r0 = n0 + (ry << 3);

    unsigned long long acc[8][4];       // [row][col-pair] f32x2 {col even, col odd}
#pragma unroll
    for (int r = 0; r < 8; r++)
#pragma unroll
        for (int c = 0; c < 4; c++) acc[r][c] = 0ULL;

    for (int ch = 0; ch < 8; ch++) {
        int kb = kbase + (ch << 5);
        if (ch) __syncthreads();
#pragma unroll
        for (int j = 0; j < 4; j++) {
            int flat = t + j * 128;     // 0..511
            int kk = flat >> 4, o4 = (flat & 15) << 2;
            float4 v = *(const float4*)(nn2w + (size_t)(kb + kk) * 64 + o4);
            unsigned u0, u1;
            CVTB2(u0, v.x, v.y);
            CVTB2(u1, v.z, v.w);
            *(uint2*)(Tsu + (kk << 5) + (o4 >> 1)) = make_uint2(u0, u1);
        }
        __syncthreads();
#pragma unroll
        for (int kq = 0; kq < 4; kq++) {
            uint4 q[8];
#pragma unroll
            for (int r = 0; r < 8; r++)
                q[r] = *(const uint4*)(g_Pb + (size_t)(r0 + r) * KK + kb + (kq << 3));
#pragma unroll
            for (int kk = 0; kk < 8; kk++) {
                uint4 tw = *(const uint4*)(Tsu + (((kq << 3) + kk) << 5) + (tx << 2));
                unsigned long long tp0, tp1, tp2, tp3;
                PACK2UU(tp0, tw.x << 16, tw.x & 0xFFFF0000u);
                PACK2UU(tp1, tw.y << 16, tw.y & 0xFFFF0000u);
                PACK2UU(tp2, tw.z << 16, tw.z & 0xFFFF0000u);
                PACK2UU(tp3, tw.w << 16, tw.w & 0xFFFF0000u);
#pragma unroll
                for (int r = 0; r < 8; r++) {
                    unsigned w = ((const unsigned*)&q[r])[kk >> 1];
                    unsigned f = (kk & 1) ? (w & 0xFFFF0000u) : (w << 16);
                    unsigned long long pd;
                    PACK2U(pd, f);
                    FMA2(acc[r][0], pd, tp0);
                    FMA2(acc[r][1], pd, tp1);
                    FMA2(acc[r][2], pd, tp2);
                    FMA2(acc[r][3], pd, tp3);
                }
            }
        }
    }

    float* gp = g_part + (size_t)ks * (NNODES * DIM) + (size_t)r0 * 64 + (tx << 3);
#pragma unroll
    for (int r = 0; r < 8; r++) {
        ulonglong2 v0, v1;
        v0.x = acc[r][0]; v0.y = acc[r][1];
        v1.x = acc[r][2]; v1.y = acc[r][3];
        *(ulonglong2*)(gp + (size_t)r * 64)     = v0;
        *(ulonglong2*)(gp + (size_t)r * 64 + 4) = v1;
    }
}

// ---------------- fused per-node: Sx via graph-sum; m; GRU -> h,out ----------------
// block = 4 nodes of one graph (4 | 20 so never straddles a graph boundary)
__global__ void k_node(const float* __restrict__ nn2b, const float* __restrict__ rootw,
                       const float* __restrict__ convb,
                       const float* __restrict__ bih, const float* __restrict__ bhh) {
    __shared__ float sx_s[4][64], out_s[4][64], h_s[4][64], m_s[4][64], gpart[4][64];
    int t = threadIdx.x;
    int ln = t >> 6, o = t & 63;
    int n = blockIdx.x * 4 + ln;
    int g = n / NPER;

    out_s[ln][o] = g_out[n * 64 + o];
    h_s[ln][o]   = g_h[n * 64 + o];
    // graph sum: each ln-group sums 5 rows
    {
        float ps = 0.0f;
        const float* gb = g_out + ((size_t)g * NPER + ln * 5) * 64 + o;
#pragma unroll
        for (int j = 0; j < 5; j++) ps += gb[j * 64];
        gpart[ln][o] = ps;
    }
    __syncthreads();
    sx_s[ln][o] = gpart[0][o] + gpart[1][o] + gpart[2][o] + gpart[3][o] - out_s[ln][o];
    __syncthreads();

    {
        float s = 0.0f;
#pragma unroll
        for (int q = 0; q < KSPLIT; q++) s += g_part[(size_t)q * (NNODES * DIM) + n * 64 + o];
        float acc = 0.0f;
#pragma unroll
        for (int i = 0; i < 64; i++) {
            s   = fmaf(sx_s[ln][i],  nn2b[i * 64 + o], s);
            acc = fmaf(out_s[ln][i], rootw[i * 64 + o], acc);
        }
        m_s[ln][o] = fmaxf(s * (1.0f / 19.0f) + acc + convb[o], 0.0f);
    }
    __syncthreads();

    {
        float gi0 = bih[o], gi1 = bih[o + 64], gi2 = bih[o + 128];
        float gh0 = bhh[o], gh1 = bhh[o + 64], gh2 = bhh[o + 128];
#pragma unroll 8
        for (int i = 0; i < 64; i++) {
            float mi = m_s[ln][i], hi = h_s[ln][i];
            const float* wiT = g_wihT + i * 192 + o;
            const float* whT = g_whhT + i * 192 + o;
            gi0 = fmaf(mi, wiT[0],   gi0);
            gi1 = fmaf(mi, wiT[64],  gi1);
            gi2 = fmaf(mi, wiT[128], gi2);
            gh0 = fmaf(hi, whT[0],   gh0);
            gh1 = fmaf(hi, whT[64],  gh1);
            gh2 = fmaf(hi, whT[128], gh2);
        }
        float r  = sigf(gi0 + gh0);
        float z  = sigf(gi1 + gh1);
        float nn = tanhf(gi2 + r * gh2);
        float h  = (1.0f - z) * nn + z * h_s[ln][o];
        g_h[n * 64 + o]   = h;
        g_out[n * 64 + o] = h;
    }
}

// ---------------- Set2Set (3 steps) + final MLP head, one block per graph ----------------
__global__ void k_s2s(const float* __restrict__ wih, const float* __restrict__ whh,
                      const float* __restrict__ bih, const float* __restrict__ bhh,
                      const float* __restrict__ l1w, const float* __restrict__ l1b,
                      const float* __restrict__ l2w, const float* __restrict__ l2b,
                      float* __restrict__ outp) {
    __shared__ float og[NPER * 64];
    __shared__ float qs[128], hl[64], cl[64], gates[256], ev[NPER], av[NPER], red[64];
    __shared__ float ssum;
    int g = blockIdx.x, t = threadIdx.x;               // 128 threads

    for (int u = t; u < NPER * 64; u += 128) og[u] = g_out[g * NPER * 64 + u];
    qs[t] = 0.0f;
    if (t < 64) { hl[t] = 0.0f; cl[t] = 0.0f; }
    __syncthreads();

    for (int step = 0; step < 3; step++) {
        for (int j = t; j < 256; j += 128) {
            float acc = bih[j] + bhh[j];
            const float* wr = wih + j * 128;
            for (int i = 0; i < 128; i++) acc = fmaf(qs[i], wr[i], acc);
            const float* w2 = whh + j * 64;
            for (int i = 0; i < 64; i++) acc = fmaf(hl[i], w2[i], acc);
            gates[j] = acc;
        }
        __syncthreads();
        if (t < 64) {
            float ig = gates[t], fg = gates[64 + t], gg = gates[128 + t], og_ = gates[192 + t];
            float c = sigf(fg) * cl[t] + sigf(ig) * tanhf(gg);
            cl[t] = c;
            hl[t] = sigf(og_) * tanhf(c);
        }
        __syncthreads();
        if (t < NPER) {
            float acc = 0.0f;
            for (int o = 0; o < 64; o++) acc = fmaf(og[t * 64 + o], hl[o], acc);
            ev[t] = acc;
        }
        __syncthreads();
        if (t == 0) {
            float mx = ev[0];
            for (int v = 1; v < NPER; v++) mx = fmaxf(mx, ev[v]);
            float s = 0.0f;
            for (int v = 0; v < NPER; v++) { av[v] = expf(ev[v] - mx); s += av[v]; }
            ssum = s;
        }
        __syncthreads();
        if (t < 64) {
            float acc = 0.0f;
            for (int v = 0; v < NPER; v++) acc = fmaf(av[v], og[v * 64 + t], acc);
            qs[t] = hl[t];
            qs[64 + t] = acc / ssum;
        }
        __syncthreads();
    }

    if (t < 64) {
        float acc = l1b[t];
        for (int i = 0; i < 128; i++) acc = fmaf(qs[i], l1w[i * 64 + t], acc);
        acc = fmaxf(acc, 0.0f);
        red[t] = acc * l2w[t];
    }
    __syncthreads();
    if (t == 0) {
        float y = l2b[0];
        for (int o = 0; o < 64; o++) y += red[o];
        outp[g] = y;
    }
}

// ---------------- host launch ----------------
extern "C" void kernel_launch(void* const* d_in, const int* in_sizes, int n_in,
                              void* d_out, int out_size) {
    const float* x       = (const float*)d_in[0];
    const float* ea      = (const float*)d_in[2];
    const float* lin0_w  = (const float*)d_in[4];
    const float* lin0_b  = (const float*)d_in[5];
    const float* nn1_w   = (const float*)d_in[6];
    const float* nn1_b   = (const float*)d_in[7];
    const float* nn2_w   = (const float*)d_in[8];
    const float* nn2_b   = (const float*)d_in[9];
    const float* root_w  = (const float*)d_in[10];
    const float* conv_b  = (const float*)d_in[11];
    const float* gru_wih = (const float*)d_in[12];
    const float* gru_whh = (const float*)d_in[13];
    const float* gru_bih = (const float*)d_in[14];
    const float* gru_bhh = (const float*)d_in[15];
    const float* lstm_wih = (const float*)d_in[16];
    const float* lstm_whh = (const float*)d_in[17];
    const float* lstm_bih = (const float*)d_in[18];
    const float* lstm_bhh = (const float*)d_in[19];
    const float* lin1_w  = (const float*)d_in[20];
    const float* lin1_b  = (const float*)d_in[21];
    const float* lin2_w  = (const float*)d_in[22];
    const float* lin2_b  = (const float*)d_in[23];
    float* outp = (float*)d_out;

    k_lin0<<<(NNODES * DIM + 255) / 256, 256>>>(x, lin0_w, lin0_b);
    k_edge<<<(NEDGE * H1DIM) / 256, 256>>>(ea, nn1_w, nn1_b);
    k_prepw<<<(64 * 192 + 255) / 256, 256>>>(gru_wih, gru_whh);

    for (int it = 0; it < 3; it++) {
        k_p<<<NNODES, 128>>>();
        k_agg<<<640, 128>>>(nn2_w);
        k_node<<<NNODES / 4, 256>>>(nn2_b, root_w, conv_b, gru_bih, gru_bhh);
    }

    k_s2s<<<NGRAPH, 128>>>(lstm_wih, lstm_whh, lstm_bih, lstm_bhh,
                           lin1_w, lin1_b, lin2_w, lin2_b, outp);
}

// round 13
// speedup vs baseline: 1.0199x; 1.0199x over previous
#include <cuda_runtime.h>
#include <cuda_bf16.h>
#include <math.h>
#include <stdint.h>

// ---------------- problem constants ----------------
#define NGRAPH 128
#define NPER   20
#define NNODES 2560          // 128*20
#define EPG    380           // 20*19
#define NEDGE  48640         // 128*380
#define DIM    64
#define H1DIM  128
#define KK     8192          // H1DIM*DIM
#define KSPLIT 32            // k_agg K-splits (each CTA covers 256 k)

// ---------------- packed f32x2 helpers (sm_100+) ----------------
#define FMA2(acc, a, b) asm("fma.rn.f32x2 %0, %1, %2, %0;" : "+l"(acc) : "l"(a), "l"(b))
#define PACK2(out, f)   asm("mov.b64 %0, {%1, %1};" : "=l"(out) : "f"(f))
#define PACK2U(out, u)  asm("mov.b64 %0, {%1, %1};" : "=l"(out) : "r"(u))
#define PACK2UU(out, a, b) asm("mov.b64 %0, {%1, %2};" : "=l"(out) : "r"(a), "r"(b))
#define UNPK2(lo, hi, p) asm("mov.b64 {%0, %1}, %2;" : "=f"(lo), "=f"(hi) : "l"(p))
#define CVTB2(out, lo, hi) asm("cvt.rn.bf16x2.f32 %0, %1, %2;" : "=r"(out) : "f"(hi), "f"(lo))

// ---------------- scratch (static device globals; no allocation) ----------------
__device__ unsigned short g_h1b[NEDGE * H1DIM];   // 12.5 MB bf16 edge MLP hidden
__device__ unsigned short g_Pb[NNODES * KK];      // 42 MB bf16 outer-product accumulators
__device__ float g_part[KSPLIT * NNODES * DIM];   // 21 MB split-K partials
__device__ float g_out[NNODES * DIM];
__device__ float g_h  [NNODES * DIM];
__device__ float g_wihT[64 * 192];                // GRU weights transposed [i][j]
__device__ float g_whhT[64 * 192];

__device__ __forceinline__ float sigf(float x) { return 1.0f / (1.0f + expf(-x)); }

// ---------------- out = relu(x @ lin0_w + b); h = out ----------------
__global__ void k_lin0(const float* __restrict__ x, const float* __restrict__ w,
                       const float* __restrict__ b) {
    int idx = blockIdx.x * 256 + threadIdx.x;
    if (idx >= NNODES * DIM) return;
    int n = idx >> 6, o = idx & 63;
    const float* xr = x + n * 11;
    float acc = b[o];
#pragma unroll
    for (int f = 0; f < 11; f++) acc = fmaf(xr[f], w[f * 64 + o], acc);
    acc = fmaxf(acc, 0.0f);
    g_out[idx] = acc;
    g_h[idx]   = acc;
}

// ---------------- h1 = relu(edge_attr @ nn1_w + nn1_b) -> bf16 ----------------
__global__ void k_edge(const float* __restrict__ ea, const float* __restrict__ w,
                       const float* __restrict__ b) {
    int idx = blockIdx.x * 256 + threadIdx.x;
    if (idx >= NEDGE * H1DIM) return;
    int e = idx >> 7, k = idx & 127;
    const float* er = ea + e * 5;
    float acc = b[k];
#pragma unroll
    for (int f = 0; f < 5; f++) acc = fmaf(er[f], w[f * 128 + k], acc);
    acc = fmaxf(acc, 0.0f);
    g_h1b[idx] = __bfloat16_as_ushort(__float2bfloat16(acc));
}

// ---------------- transpose GRU weights (once) ----------------
__global__ void k_prepw(const float* __restrict__ wih, const float* __restrict__ whh) {
    int idx = blockIdx.x * 256 + threadIdx.x;
    if (idx >= 64 * 192) return;
    int i = idx / 192, j = idx % 192;
    g_wihT[idx] = wih[j * 64 + i];
    g_whhT[idx] = whh[j * 64 + i];
}

// ---------------- P[d] = sum_s h1[s->d] (outer) out[s] -> bf16 ----------------
// 128 threads; thread tile 8 k x 8 i; operands from global, software-pipelined
// (prefetch s+1 loads before computing s: MLP=2 hides the L2 round trip)
__global__ void __launch_bounds__(128) k_p() {
    int n = blockIdx.x;
    int g = n / NPER, d = n % NPER;
    int t = threadIdx.x;
    int kg = t >> 3, ig = t & 7;        // k = kg*8..+7, i = ig*8..+7
    const float* xbase = g_out + (size_t)g * NPER * 64 + (ig << 3);
    const unsigned short* hbase = g_h1b + (size_t)g * EPG * 128 + (kg << 3);

    unsigned long long acc[8][4];       // [k][i-pair] f32x2
#pragma unroll
    for (int k = 0; k < 8; k++)
#pragma unroll
        for (int c = 0; c < 4; c++) acc[k][c] = 0ULL;

    // prologue: loads for sI=0
    int s0 = 0 + (0 >= d);
    int j0 = (d < s0) ? d : d - 1;
    ulonglong2 xa = *(const ulonglong2*)(xbase + s0 * 64);
    ulonglong2 xb = *(const ulonglong2*)(xbase + s0 * 64 + 4);
    uint4 hq = *(const uint4*)(hbase + (size_t)(s0 * 19 + j0) * 128);

    for (int sI = 0; sI < 19; sI++) {
        // prefetch next iteration's operands
        ulonglong2 xa2, xb2;
        uint4 hq2;
        if (sI < 18) {
            int sn = (sI + 1) + ((sI + 1) >= d);
            int jn = (d < sn) ? d : d - 1;
            xa2 = *(const ulonglong2*)(xbase + sn * 64);
            xb2 = *(const ulonglong2*)(xbase + sn * 64 + 4);
            hq2 = *(const uint4*)(hbase + (size_t)(sn * 19 + jn) * 128);
        }
        unsigned hw[4] = {hq.x, hq.y, hq.z, hq.w};
#pragma unroll
        for (int p = 0; p < 4; p++) {
            unsigned long long plo, phi;
            PACK2U(plo, hw[p] << 16);
            PACK2U(phi, hw[p] & 0xFFFF0000u);
            int k0 = p << 1, k1 = k0 + 1;
            FMA2(acc[k0][0], plo, xa.x); FMA2(acc[k0][1], plo, xa.y);
            FMA2(acc[k0][2], plo, xb.x); FMA2(acc[k0][3], plo, xb.y);
            FMA2(acc[k1][0], phi, xa.x); FMA2(acc[k1][1], phi, xa.y);
            FMA2(acc[k1][2], phi, xb.x); FMA2(acc[k1][3], phi, xb.y);
        }
        xa = xa2; xb = xb2; hq = hq2;
    }

    unsigned short* pd = g_Pb + (size_t)n * KK + (ig << 3);
#pragma unroll
    for (int k = 0; k < 8; k++) {
        unsigned o0, o1, o2, o3;
        float lo, hi;
        UNPK2(lo, hi, acc[k][0]); CVTB2(o0, lo, hi);
        UNPK2(lo, hi, acc[k][1]); CVTB2(o1, lo, hi);
        UNPK2(lo, hi, acc[k][2]); CVTB2(o2, lo, hi);
        UNPK2(lo, hi, acc[k][3]); CVTB2(o3, lo, hi);
        *(uint4*)(pd + ((kg << 3) + k) * 64) = make_uint4(o0, o1, o2, o3);
    }
}

// ---------------- k_agg: partial[ks] = Pb[128-row tile] @ T over 256-k slice ----------------
__global__ void __launch_bounds__(128, 4) k_agg(const float* __restrict__ nn2w) {
    __shared__ unsigned Tsu[32 * 32];   // 4 KB: [k][col-pair] bf16x2
    int bx = blockIdx.x;
    int tile = bx >> 5, ks = bx & 31;
    int n0 = tile * 128;
    int kbase = ks * 256;
    int t = threadIdx.x;
    int tx = t & 7, ry = t >> 3;        // cols tx*8..+7, rows ry*8..+7
    int r0 = n0 + (ry << 3);

    unsigned long long acc[8][4];       // [row][col-pair] f32x2 {col even, col odd}
#pragma unroll
    for (int r = 0; r < 8; r++)
#pragma unroll
        for (int c = 0; c < 4; c++) acc[r][c] = 0ULL;

    for (int ch = 0; ch < 8; ch++) {
        int kb = kbase + (ch << 5);
        if (ch) __syncthreads();
#pragma unroll
        for (int j = 0; j < 4; j++) {
            int flat = t + j * 128;     // 0..511
            int kk = flat >> 4, o4 = (flat & 15) << 2;
            float4 v = *(const float4*)(nn2w + (size_t)(kb + kk) * 64 + o4);
            unsigned u0, u1;
            CVTB2(u0, v.x, v.y);
            CVTB2(u1, v.z, v.w);
            *(uint2*)(Tsu + (kk << 5) + (o4 >> 1)) = make_uint2(u0, u1);
        }
        __syncthreads();
#pragma unroll
        for (int kq = 0; kq < 4; kq++) {
            uint4 q[8];
#pragma unroll
            for (int r = 0; r < 8; r++)
                q[r] = *(const uint4*)(g_Pb + (size_t)(r0 + r) * KK + kb + (kq << 3));
#pragma unroll
            for (int kk = 0; kk < 8; kk++) {
                uint4 tw = *(const uint4*)(Tsu + (((kq << 3) + kk) << 5) + (tx << 2));
                unsigned long long tp0, tp1, tp2, tp3;
                PACK2UU(tp0, tw.x << 16, tw.x & 0xFFFF0000u);
                PACK2UU(tp1, tw.y << 16, tw.y & 0xFFFF0000u);
                PACK2UU(tp2, tw.z << 16, tw.z & 0xFFFF0000u);
                PACK2UU(tp3, tw.w << 16, tw.w & 0xFFFF0000u);
#pragma unroll
                for (int r = 0; r < 8; r++) {
                    unsigned w = ((const unsigned*)&q[r])[kk >> 1];
                    unsigned f = (kk & 1) ? (w & 0xFFFF0000u) : (w << 16);
                    unsigned long long pd;
                    PACK2U(pd, f);
                    FMA2(acc[r][0], pd, tp0);
                    FMA2(acc[r][1], pd, tp1);
                    FMA2(acc[r][2], pd, tp2);
                    FMA2(acc[r][3], pd, tp3);
                }
            }
        }
    }

    float* gp = g_part + (size_t)ks * (NNODES * DIM) + (size_t)r0 * 64 + (tx << 3);
#pragma unroll
    for (int r = 0; r < 8; r++) {
        ulonglong2 v0, v1;
        v0.x = acc[r][0]; v0.y = acc[r][1];
        v1.x = acc[r][2]; v1.y = acc[r][3];
        *(ulonglong2*)(gp + (size_t)r * 64)     = v0;
        *(ulonglong2*)(gp + (size_t)r * 64 + 4) = v1;
    }
}

// ---------------- fused per-node: Sx via graph-sum; m; GRU -> h,out ----------------
// block = 4 nodes of one graph (4 | 20 so never straddles a graph boundary)
__global__ void k_node(const float* __restrict__ nn2b, const float* __restrict__ rootw,
                       const float* __restrict__ convb,
                       const float* __restrict__ bih, const float* __restrict__ bhh) {
    __shared__ float sx_s[4][64], out_s[4][64], h_s[4][64], m_s[4][64], gpart[4][64];
    int t = threadIdx.x;
    int ln = t >> 6, o = t & 63;
    int n = blockIdx.x * 4 + ln;
    int g = n / NPER;

    out_s[ln][o] = g_out[n * 64 + o];
    h_s[ln][o]   = g_h[n * 64 + o];
    // graph sum: each ln-group sums 5 rows
    {
        float ps = 0.0f;
        const float* gb = g_out + ((size_t)g * NPER + ln * 5) * 64 + o;
#pragma unroll
        for (int j = 0; j < 5; j++) ps += gb[j * 64];
        gpart[ln][o] = ps;
    }
    __syncthreads();
    sx_s[ln][o] = gpart[0][o] + gpart[1][o] + gpart[2][o] + gpart[3][o] - out_s[ln][o];
    __syncthreads();

    {
        float s = 0.0f;
#pragma unroll
        for (int q = 0; q < KSPLIT; q++) s += g_part[(size_t)q * (NNODES * DIM) + n * 64 + o];
        float acc = 0.0f;
#pragma unroll
        for (int i = 0; i < 64; i++) {
            s   = fmaf(sx_s[ln][i],  nn2b[i * 64 + o], s);
            acc = fmaf(out_s[ln][i], rootw[i * 64 + o], acc);
        }
        m_s[ln][o] = fmaxf(s * (1.0f / 19.0f) + acc + convb[o], 0.0f);
    }
    __syncthreads();

    {
        float gi0 = bih[o], gi1 = bih[o + 64], gi2 = bih[o + 128];
        float gh0 = bhh[o], gh1 = bhh[o + 64], gh2 = bhh[o + 128];
#pragma unroll 8
        for (int i = 0; i < 64; i++) {
            float mi = m_s[ln][i], hi = h_s[ln][i];
            const float* wiT = g_wihT + i * 192 + o;
            const float* whT = g_whhT + i * 192 + o;
            gi0 = fmaf(mi, wiT[0],   gi0);
            gi1 = fmaf(mi, wiT[64],  gi1);
            gi2 = fmaf(mi, wiT[128], gi2);
            gh0 = fmaf(hi, whT[0],   gh0);
            gh1 = fmaf(hi, whT[64],  gh1);
            gh2 = fmaf(hi, whT[128], gh2);
        }
        float r  = sigf(gi0 + gh0);
        float z  = sigf(gi1 + gh1);
        float nn = tanhf(gi2 + r * gh2);
        float h  = (1.0f - z) * nn + z * h_s[ln][o];
        g_h[n * 64 + o]   = h;
        g_out[n * 64 + o] = h;
    }
}

// ---------------- Set2Set (3 steps) + final MLP head, one block per graph ----------------
__global__ void k_s2s(const float* __restrict__ wih, const float* __restrict__ whh,
                      const float* __restrict__ bih, const float* __restrict__ bhh,
                      const float* __restrict__ l1w, const float* __restrict__ l1b,
                      const float* __restrict__ l2w, const float* __restrict__ l2b,
                      float* __restrict__ outp) {
    __shared__ float og[NPER * 64];
    __shared__ float qs[128], hl[64], cl[64], gates[256], ev[NPER], av[NPER], red[64];
    __shared__ float ssum;
    int g = blockIdx.x, t = threadIdx.x;               // 128 threads

    for (int u = t; u < NPER * 64; u += 128) og[u] = g_out[g * NPER * 64 + u];
    qs[t] = 0.0f;
    if (t < 64) { hl[t] = 0.0f; cl[t] = 0.0f; }
    __syncthreads();

    for (int step = 0; step < 3; step++) {
        for (int j = t; j < 256; j += 128) {
            float acc = bih[j] + bhh[j];
            const float* wr = wih + j * 128;
            for (int i = 0; i < 128; i++) acc = fmaf(qs[i], wr[i], acc);
            const float* w2 = whh + j * 64;
            for (int i = 0; i < 64; i++) acc = fmaf(hl[i], w2[i], acc);
            gates[j] = acc;
        }
        __syncthreads();
        if (t < 64) {
            float ig = gates[t], fg = gates[64 + t], gg = gates[128 + t], og_ = gates[192 + t];
            float c = sigf(fg) * cl[t] + sigf(ig) * tanhf(gg);
            cl[t] = c;
            hl[t] = sigf(og_) * tanhf(c);
        }
        __syncthreads();
        if (t < NPER) {
            float acc = 0.0f;
            for (int o = 0; o < 64; o++) acc = fmaf(og[t * 64 + o], hl[o], acc);
            ev[t] = acc;
        }
        __syncthreads();
        if (t == 0) {
            float mx = ev[0];
            for (int v = 1; v < NPER; v++) mx = fmaxf(mx, ev[v]);
            float s = 0.0f;
            for (int v = 0; v < NPER; v++) { av[v] = expf(ev[v] - mx); s += av[v]; }
            ssum = s;
        }
        __syncthreads();
        if (t < 64) {
            float acc = 0.0f;
            for (int v = 0; v < NPER; v++) acc = fmaf(av[v], og[v * 64 + t], acc);
            qs[t] = hl[t];
            qs[64 + t] = acc / ssum;
        }
        __syncthreads();
    }

    if (t < 64) {
        float acc = l1b[t];
        for (int i = 0; i < 128; i++) acc = fmaf(qs[i], l1w[i * 64 + t], acc);
        acc = fmaxf(acc, 0.0f);
        red[t] = acc * l2w[t];
    }
    __syncthreads();
    if (t == 0) {
        float y = l2b[0];
        for (int o = 0; o < 64; o++) y += red[o];
        outp[g] = y;
    }
}

// ---------------- host launch ----------------
extern "C" void kernel_launch(void* const* d_in, const int* in_sizes, int n_in,
                              void* d_out, int out_size) {
    const float* x       = (const float*)d_in[0];
    const float* ea      = (const float*)d_in[2];
    const float* lin0_w  = (const float*)d_in[4];
    const float* lin0_b  = (const float*)d_in[5];
    const float* nn1_w   = (const float*)d_in[6];
    const float* nn1_b   = (const float*)d_in[7];
    const float* nn2_w   = (const float*)d_in[8];
    const float* nn2_b   = (const float*)d_in[9];
    const float* root_w  = (const float*)d_in[10];
    const float* conv_b  = (const float*)d_in[11];
    const float* gru_wih = (const float*)d_in[12];
    const float* gru_whh = (const float*)d_in[13];
    const float* gru_bih = (const float*)d_in[14];
    const float* gru_bhh = (const float*)d_in[15];
    const float* lstm_wih = (const float*)d_in[16];
    const float* lstm_whh = (const float*)d_in[17];
    const float* lstm_bih = (const float*)d_in[18];
    const float* lstm_bhh = (const float*)d_in[19];
    const float* lin1_w  = (const float*)d_in[20];
    const float* lin1_b  = (const float*)d_in[21];
    const float* lin2_w  = (const float*)d_in[22];
    const float* lin2_b  = (const float*)d_in[23];
    float* outp = (float*)d_out;

    k_lin0<<<(NNODES * DIM + 255) / 256, 256>>>(x, lin0_w, lin0_b);
    k_edge<<<(NEDGE * H1DIM) / 256, 256>>>(ea, nn1_w, nn1_b);
    k_prepw<<<(64 * 192 + 255) / 256, 256>>>(gru_wih, gru_whh);

    for (int it = 0; it < 3; it++) {
        k_p<<<NNODES, 128>>>();
        k_agg<<<640, 128>>>(nn2_w);
        k_node<<<NNODES / 4, 256>>>(nn2_b, root_w, conv_b, gru_bih, gru_bhh);
    }

    k_s2s<<<NGRAPH, 128>>>(lstm_wih, lstm_whh, lstm_bih, lstm_bhh,
                           lin1_w, lin1_b, lin2_w, lin2_b, outp);
}

// round 14
// speedup vs baseline: 1.0479x; 1.0275x over previous
#include <cuda_runtime.h>
#include <cuda_bf16.h>
#include <math.h>
#include <stdint.h>

// ---------------- problem constants ----------------
#define NGRAPH 128
#define NPER   20
#define NNODES 2560          // 128*20
#define EPG    380           // 20*19
#define NEDGE  48640         // 128*380
#define DIM    64
#define H1DIM  128
#define KK     8192          // H1DIM*DIM
#define KSPLIT 64            // k_agg K-splits (each CTA covers 128 k)

// ---------------- packed f32x2 helpers (sm_100+) ----------------
#define FMA2(acc, a, b) asm("fma.rn.f32x2 %0, %1, %2, %0;" : "+l"(acc) : "l"(a), "l"(b))
#define PACK2(out, f)   asm("mov.b64 %0, {%1, %1};" : "=l"(out) : "f"(f))
#define PACK2U(out, u)  asm("mov.b64 %0, {%1, %1};" : "=l"(out) : "r"(u))
#define PACK2UU(out, a, b) asm("mov.b64 %0, {%1, %2};" : "=l"(out) : "r"(a), "r"(b))
#define UNPK2(lo, hi, p) asm("mov.b64 {%0, %1}, %2;" : "=f"(lo), "=f"(hi) : "l"(p))
#define CVTB2(out, lo, hi) asm("cvt.rn.bf16x2.f32 %0, %1, %2;" : "=r"(out) : "f"(hi), "f"(lo))

// ---------------- scratch (static device globals; no allocation) ----------------
__device__ unsigned short g_h1b[NEDGE * H1DIM];   // 12.5 MB bf16 edge MLP hidden
__device__ unsigned short g_Pb[NNODES * KK];      // 42 MB bf16 outer-product accumulators
__device__ float g_part[KSPLIT * NNODES * DIM];   // 42 MB split-K partials
__device__ float g_out[NNODES * DIM];
__device__ float g_h  [NNODES * DIM];
__device__ float g_wihT[64 * 192];                // GRU weights transposed [i][j]
__device__ float g_whhT[64 * 192];
__device__ float g_lwihT[128 * 256];              // LSTM w_ih transposed [i][j]
__device__ float g_lwhhT[64 * 256];               // LSTM w_hh transposed [i][j]

__device__ __forceinline__ float sigf(float x) { return 1.0f / (1.0f + expf(-x)); }

// ---------------- out = relu(x @ lin0_w + b); h = out ----------------
__global__ void k_lin0(const float* __restrict__ x, const float* __restrict__ w,
                       const float* __restrict__ b) {
    int idx = blockIdx.x * 256 + threadIdx.x;
    if (idx >= NNODES * DIM) return;
    int n = idx >> 6, o = idx & 63;
    const float* xr = x + n * 11;
    float acc = b[o];
#pragma unroll
    for (int f = 0; f < 11; f++) acc = fmaf(xr[f], w[f * 64 + o], acc);
    acc = fmaxf(acc, 0.0f);
    g_out[idx] = acc;
    g_h[idx]   = acc;
}

// ---------------- h1 = relu(edge_attr @ nn1_w + nn1_b) -> bf16 ----------------
__global__ void k_edge(const float* __restrict__ ea, const float* __restrict__ w,
                       const float* __restrict__ b) {
    int idx = blockIdx.x * 256 + threadIdx.x;
    if (idx >= NEDGE * H1DIM) return;
    int e = idx >> 7, k = idx & 127;
    const float* er = ea + e * 5;
    float acc = b[k];
#pragma unroll
    for (int f = 0; f < 5; f++) acc = fmaf(er[f], w[f * 128 + k], acc);
    acc = fmaxf(acc, 0.0f);
    g_h1b[idx] = __bfloat16_as_ushort(__float2bfloat16(acc));
}

// ---------------- transpose GRU + LSTM weights (once) ----------------
__global__ void k_prepw(const float* __restrict__ wih, const float* __restrict__ whh,
                        const float* __restrict__ lwih, const float* __restrict__ lwhh) {
    int idx = blockIdx.x * 256 + threadIdx.x;
    if (idx < 64 * 192) {
        int i = idx / 192, j = idx % 192;
        g_wihT[idx] = wih[j * 64 + i];
        g_whhT[idx] = whh[j * 64 + i];
    }
    if (idx < 128 * 256) {
        int i = idx >> 8, j = idx & 255;
        g_lwihT[idx] = lwih[j * 128 + i];
    }
    if (idx < 64 * 256) {
        int i = idx >> 8, j = idx & 255;
        g_lwhhT[idx] = lwhh[j * 64 + i];
    }
}

// ---------------- P[d] = sum_s h1[s->d] (outer) out[s] -> bf16 ----------------
// 128 threads; thread tile 8 k x 8 i; operands from global, software-pipelined
__global__ void __launch_bounds__(128) k_p() {
    int n = blockIdx.x;
    int g = n / NPER, d = n % NPER;
    int t = threadIdx.x;
    int kg = t >> 3, ig = t & 7;        // k = kg*8..+7, i = ig*8..+7
    const float* xbase = g_out + (size_t)g * NPER * 64 + (ig << 3);
    const unsigned short* hbase = g_h1b + (size_t)g * EPG * 128 + (kg << 3);

    unsigned long long acc[8][4];       // [k][i-pair] f32x2
#pragma unroll
    for (int k = 0; k < 8; k++)
#pragma unroll
        for (int c = 0; c < 4; c++) acc[k][c] = 0ULL;

    int s0 = 0 + (0 >= d);
    int j0 = (d < s0) ? d : d - 1;
    ulonglong2 xa = *(const ulonglong2*)(xbase + s0 * 64);
    ulonglong2 xb = *(const ulonglong2*)(xbase + s0 * 64 + 4);
    uint4 hq = *(const uint4*)(hbase + (size_t)(s0 * 19 + j0) * 128);

    for (int sI = 0; sI < 19; sI++) {
        ulonglong2 xa2, xb2;
        uint4 hq2;
        if (sI < 18) {
            int sn = (sI + 1) + ((sI + 1) >= d);
            int jn = (d < sn) ? d : d - 1;
            xa2 = *(const ulonglong2*)(xbase + sn * 64);
            xb2 = *(const ulonglong2*)(xbase + sn * 64 + 4);
            hq2 = *(const uint4*)(hbase + (size_t)(sn * 19 + jn) * 128);
        }
        unsigned hw[4] = {hq.x, hq.y, hq.z, hq.w};
#pragma unroll
        for (int p = 0; p < 4; p++) {
            unsigned long long plo, phi;
            PACK2U(plo, hw[p] << 16);
            PACK2U(phi, hw[p] & 0xFFFF0000u);
            int k0 = p << 1, k1 = k0 + 1;
            FMA2(acc[k0][0], plo, xa.x); FMA2(acc[k0][1], plo, xa.y);
            FMA2(acc[k0][2], plo, xb.x); FMA2(acc[k0][3], plo, xb.y);
            FMA2(acc[k1][0], phi, xa.x); FMA2(acc[k1][1], phi, xa.y);
            FMA2(acc[k1][2], phi, xb.x); FMA2(acc[k1][3], phi, xb.y);
        }
        xa = xa2; xb = xb2; hq = hq2;
    }

    unsigned short* pd = g_Pb + (size_t)n * KK + (ig << 3);
#pragma unroll
    for (int k = 0; k < 8; k++) {
        unsigned o0, o1, o2, o3;
        float lo, hi;
        UNPK2(lo, hi, acc[k][0]); CVTB2(o0, lo, hi);
        UNPK2(lo, hi, acc[k][1]); CVTB2(o1, lo, hi);
        UNPK2(lo, hi, acc[k][2]); CVTB2(o2, lo, hi);
        UNPK2(lo, hi, acc[k][3]); CVTB2(o3, lo, hi);
        *(uint4*)(pd + ((kg << 3) + k) * 64) = make_uint4(o0, o1, o2, o3);
    }
}

// ---------------- k_agg: partial[ks] = Pb[128-row tile] @ T over 128-k slice ----------------
// grid 1280 = 20 tiles x 64 K-splits (balanced waves); 128 threads; tile 8r x 8c
__global__ void __launch_bounds__(128, 4) k_agg(const float* __restrict__ nn2w) {
    __shared__ unsigned Tsu[32 * 32];   // 4 KB: [k][col-pair] bf16x2
    int bx = blockIdx.x;
    int tile = bx >> 6, ks = bx & 63;
    int n0 = tile * 128;
    int kbase = ks * 128;
    int t = threadIdx.x;
    int tx = t & 7, ry = t >> 3;        // cols tx*8..+7, rows ry*8..+7
    int r0 = n0 + (ry << 3);

    unsigned long long acc[8][4];       // [row][col-pair] f32x2 {col even, col odd}
#pragma unroll
    for (int r = 0; r < 8; r++)
#pragma unroll
        for (int c = 0; c < 4; c++) acc[r][c] = 0ULL;

    for (int ch = 0; ch < 4; ch++) {
        int kb = kbase + (ch << 5);
        if (ch) __syncthreads();
#pragma unroll
        for (int j = 0; j < 4; j++) {
            int flat = t + j * 128;     // 0..511
            int kk = flat >> 4, o4 = (flat & 15) << 2;
            float4 v = *(const float4*)(nn2w + (size_t)(kb + kk) * 64 + o4);
            unsigned u0, u1;
            CVTB2(u0, v.x, v.y);
            CVTB2(u1, v.z, v.w);
            *(uint2*)(Tsu + (kk << 5) + (o4 >> 1)) = make_uint2(u0, u1);
        }
        __syncthreads();
#pragma unroll
        for (int kq = 0; kq < 4; kq++) {
            uint4 q[8];
#pragma unroll
            for (int r = 0; r < 8; r++)
                q[r] = *(const uint4*)(g_Pb + (size_t)(r0 + r) * KK + kb + (kq << 3));
#pragma unroll
            for (int kk = 0; kk < 8; kk++) {
                uint4 tw = *(const uint4*)(Tsu + (((kq << 3) + kk) << 5) + (tx << 2));
                unsigned long long tp0, tp1, tp2, tp3;
                PACK2UU(tp0, tw.x << 16, tw.x & 0xFFFF0000u);
                PACK2UU(tp1, tw.y << 16, tw.y & 0xFFFF0000u);
                PACK2UU(tp2, tw.z << 16, tw.z & 0xFFFF0000u);
                PACK2UU(tp3, tw.w << 16, tw.w & 0xFFFF0000u);
#pragma unroll
                for (int r = 0; r < 8; r++) {
                    unsigned w = ((const unsigned*)&q[r])[kk >> 1];
                    unsigned f = (kk & 1) ? (w & 0xFFFF0000u) : (w << 16);
                    unsigned long long pd;
                    PACK2U(pd, f);
                    FMA2(acc[r][0], pd, tp0);
                    FMA2(acc[r][1], pd, tp1);
                    FMA2(acc[r][2], pd, tp2);
                    FMA2(acc[r][3], pd, tp3);
                }
            }
        }
    }

    float* gp = g_part + (size_t)ks * (NNODES * DIM) + (size_t)r0 * 64 + (tx << 3);
#pragma unroll
    for (int r = 0; r < 8; r++) {
        ulonglong2 v0, v1;
        v0.x = acc[r][0]; v0.y = acc[r][1];
        v1.x = acc[r][2]; v1.y = acc[r][3];
        *(ulonglong2*)(gp + (size_t)r * 64)     = v0;
        *(ulonglong2*)(gp + (size_t)r * 64 + 4) = v1;
    }
}

// ---------------- fused per-node: Sx via graph-sum; m; GRU -> h,out ----------------
__global__ void k_node(const float* __restrict__ nn2b, const float* __restrict__ rootw,
                       const float* __restrict__ convb,
                       const float* __restrict__ bih, const float* __restrict__ bhh) {
    __shared__ float sx_s[4][64], out_s[4][64], h_s[4][64], m_s[4][64], gpart[4][64];
    int t = threadIdx.x;
    int ln = t >> 6, o = t & 63;
    int n = blockIdx.x * 4 + ln;
    int g = n / NPER;

    out_s[ln][o] = g_out[n * 64 + o];
    h_s[ln][o]   = g_h[n * 64 + o];
    {
        float ps = 0.0f;
        const float* gb = g_out + ((size_t)g * NPER + ln * 5) * 64 + o;
#pragma unroll
        for (int j = 0; j < 5; j++) ps += gb[j * 64];
        gpart[ln][o] = ps;
    }
    __syncthreads();
    sx_s[ln][o] = gpart[0][o] + gpart[1][o] + gpart[2][o] + gpart[3][o] - out_s[ln][o];
    __syncthreads();

    {
        float s = 0.0f;
#pragma unroll
        for (int q = 0; q < KSPLIT; q++) s += g_part[(size_t)q * (NNODES * DIM) + n * 64 + o];
        float acc = 0.0f;
#pragma unroll
        for (int i = 0; i < 64; i++) {
            s   = fmaf(sx_s[ln][i],  nn2b[i * 64 + o], s);
            acc = fmaf(out_s[ln][i], rootw[i * 64 + o], acc);
        }
        m_s[ln][o] = fmaxf(s * (1.0f / 19.0f) + acc + convb[o], 0.0f);
    }
    __syncthreads();

    {
        float gi0 = bih[o], gi1 = bih[o + 64], gi2 = bih[o + 128];
        float gh0 = bhh[o], gh1 = bhh[o + 64], gh2 = bhh[o + 128];
#pragma unroll 8
        for (int i = 0; i < 64; i++) {
            float mi = m_s[ln][i], hi = h_s[ln][i];
            const float* wiT = g_wihT + i * 192 + o;
            const float* whT = g_whhT + i * 192 + o;
            gi0 = fmaf(mi, wiT[0],   gi0);
            gi1 = fmaf(mi, wiT[64],  gi1);
            gi2 = fmaf(mi, wiT[128], gi2);
            gh0 = fmaf(hi, whT[0],   gh0);
            gh1 = fmaf(hi, whT[64],  gh1);
            gh2 = fmaf(hi, whT[128], gh2);
        }
        float r  = sigf(gi0 + gh0);
        float z  = sigf(gi1 + gh1);
        float nn = tanhf(gi2 + r * gh2);
        float h  = (1.0f - z) * nn + z * h_s[ln][o];
        g_h[n * 64 + o]   = h;
        g_out[n * 64 + o] = h;
    }
}

// ---------------- Set2Set (3 steps) + final MLP head, one block per graph ----------------
// LSTM gate GEMVs use transposed weights (coalesced); same summation order
__global__ void k_s2s(const float* __restrict__ bih, const float* __restrict__ bhh,
                      const float* __restrict__ l1w, const float* __restrict__ l1b,
                      const float* __restrict__ l2w, const float* __restrict__ l2b,
                      float* __restrict__ outp) {
    __shared__ float og[NPER * 64];
    __shared__ float qs[128], hl[64], cl[64], gates[256], ev[NPER], av[NPER], red[64];
    __shared__ float ssum;
    int g = blockIdx.x, t = threadIdx.x;               // 128 threads

    for (int u = t; u < NPER * 64; u += 128) og[u] = g_out[g * NPER * 64 + u];
    qs[t] = 0.0f;
    if (t < 64) { hl[t] = 0.0f; cl[t] = 0.0f; }
    __syncthreads();

    for (int step = 0; step < 3; step++) {
#pragma unroll
        for (int jj = 0; jj < 2; jj++) {
            int j = t + jj * 128;
            float acc = bih[j] + bhh[j];
            for (int i = 0; i < 128; i++) acc = fmaf(qs[i], g_lwihT[i * 256 + j], acc);
            for (int i = 0; i < 64; i++)  acc = fmaf(hl[i], g_lwhhT[i * 256 + j], acc);
            gates[j] = acc;
        }
        __syncthreads();
        if (t < 64) {
            float ig = gates[t], fg = gates[64 + t], gg = gates[128 + t], og_ = gates[192 + t];
            float c = sigf(fg) * cl[t] + sigf(ig) * tanhf(gg);
            cl[t] = c;
            hl[t] = sigf(og_) * tanhf(c);
        }
        __syncthreads();
        if (t < NPER) {
            float acc = 0.0f;
            for (int o = 0; o < 64; o++) acc = fmaf(og[t * 64 + o], hl[o], acc);
            ev[t] = acc;
        }
        __syncthreads();
        if (t == 0) {
            float mx = ev[0];
            for (int v = 1; v < NPER; v++) mx = fmaxf(mx, ev[v]);
            float s = 0.0f;
            for (int v = 0; v < NPER; v++) { av[v] = expf(ev[v] - mx); s += av[v]; }
            ssum = s;
        }
        __syncthreads();
        if (t < 64) {
            float acc = 0.0f;
            for (int v = 0; v < NPER; v++) acc = fmaf(av[v], og[v * 64 + t], acc);
            qs[t] = hl[t];
            qs[64 + t] = acc / ssum;
        }
        __syncthreads();
    }

    if (t < 64) {
        float acc = l1b[t];
        for (int i = 0; i < 128; i++) acc = fmaf(qs[i], l1w[i * 64 + t], acc);
        acc = fmaxf(acc, 0.0f);
        red[t] = acc * l2w[t];
    }
    __syncthreads();
    if (t == 0) {
        float y = l2b[0];
        for (int o = 0; o < 64; o++) y += red[o];
        outp[g] = y;
    }
}

// ---------------- host launch ----------------
extern "C" void kernel_launch(void* const* d_in, const int* in_sizes, int n_in,
                              void* d_out, int out_size) {
    const float* x       = (const float*)d_in[0];
    const float* ea      = (const float*)d_in[2];
    const float* lin0_w  = (const float*)d_in[4];
    const float* lin0_b  = (const float*)d_in[5];
    const float* nn1_w   = (const float*)d_in[6];
    const float* nn1_b   = (const float*)d_in[7];
    const float* nn2_w   = (const float*)d_in[8];
    const float* nn2_b   = (const float*)d_in[9];
    const float* root_w  = (const float*)d_in[10];
    const float* conv_b  = (const float*)d_in[11];
    const float* gru_wih = (const float*)d_in[12];
    const float* gru_whh = (const float*)d_in[13];
    const float* gru_bih = (const float*)d_in[14];
    const float* gru_bhh = (const float*)d_in[15];
    const float* lstm_wih = (const float*)d_in[16];
    const float* lstm_whh = (const float*)d_in[17];
    const float* lstm_bih = (const float*)d_in[18];
    const float* lstm_bhh = (const float*)d_in[19];
    const float* lin1_w  = (const float*)d_in[20];
    const float* lin1_b  = (const float*)d_in[21];
    const float* lin2_w  = (const float*)d_in[22];
    const float* lin2_b  = (const float*)d_in[23];
    float* outp = (float*)d_out;

    k_lin0<<<(NNODES * DIM + 255) / 256, 256>>>(x, lin0_w, lin0_b);
    k_edge<<<(NEDGE * H1DIM) / 256, 256>>>(ea, nn1_w, nn1_b);
    k_prepw<<<(128 * 256 + 255) / 256, 256>>>(gru_wih, gru_whh, lstm_wih, lstm_whh);

    for (int it = 0; it < 3; it++) {
        k_p<<<NNODES, 128>>>();
        k_agg<<<1280, 128>>>(nn2_w);
        k_node<<<NNODES / 4, 256>>>(nn2_b, root_w, conv_b, gru_bih, gru_bhh);
    }

    k_s2s<<<NGRAPH, 128>>>(lstm_bih, lstm_bhh, lin1_w, lin1_b, lin2_w, lin2_b, outp);
}

// round 16
// speedup vs baseline: 1.0482x; 1.0003x over previous
#include <cuda_runtime.h>
#include <cuda_bf16.h>
#include <math.h>
#include <stdint.h>

// ---------------- problem constants ----------------
#define NGRAPH 128
#define NPER   20
#define NNODES 2560          // 128*20
#define EPG    380           // 20*19
#define NEDGE  48640         // 128*380
#define DIM    64
#define H1DIM  128
#define KK     8192          // H1DIM*DIM
#define KSPLIT 32            // k_agg K-splits (each CTA covers 256 k)

// ---------------- packed f32x2 helpers (sm_100+) ----------------
#define FMA2(acc, a, b) asm("fma.rn.f32x2 %0, %1, %2, %0;" : "+l"(acc) : "l"(a), "l"(b))
#define PACK2(out, f)   asm("mov.b64 %0, {%1, %1};" : "=l"(out) : "f"(f))
#define PACK2U(out, u)  asm("mov.b64 %0, {%1, %1};" : "=l"(out) : "r"(u))
#define PACK2UU(out, a, b) asm("mov.b64 %0, {%1, %2};" : "=l"(out) : "r"(a), "r"(b))
#define UNPK2(lo, hi, p) asm("mov.b64 {%0, %1}, %2;" : "=f"(lo), "=f"(hi) : "l"(p))
#define CVTB2(out, lo, hi) asm("cvt.rn.bf16x2.f32 %0, %1, %2;" : "=r"(out) : "f"(hi), "f"(lo))

// ---------------- scratch (static device globals; no allocation) ----------------
__device__ unsigned short g_h1b[NEDGE * H1DIM];   // 12.5 MB bf16 edge MLP hidden
__device__ unsigned short g_Pb[NNODES * KK];      // 42 MB bf16 outer-product accumulators
__device__ float g_part[KSPLIT * NNODES * DIM];   // 21 MB split-K partials
__device__ float g_out[NNODES * DIM];
__device__ float g_h  [NNODES * DIM];
__device__ float g_wihT[64 * 192];                // GRU weights transposed [i][j]
__device__ float g_whhT[64 * 192];
__device__ float g_lwihT[128 * 256];              // LSTM w_ih transposed [i][j]
__device__ float g_lwhhT[64 * 256];               // LSTM w_hh transposed [i][j]

__device__ __forceinline__ float sigf(float x) { return 1.0f / (1.0f + expf(-x)); }

// ---------------- out = relu(x @ lin0_w + b); h = out ----------------
__global__ void k_lin0(const float* __restrict__ x, const float* __restrict__ w,
                       const float* __restrict__ b) {
    int idx = blockIdx.x * 256 + threadIdx.x;
    if (idx >= NNODES * DIM) return;
    int n = idx >> 6, o = idx & 63;
    const float* xr = x + n * 11;
    float acc = b[o];
#pragma unroll
    for (int f = 0; f < 11; f++) acc = fmaf(xr[f], w[f * 64 + o], acc);
    acc = fmaxf(acc, 0.0f);
    g_out[idx] = acc;
    g_h[idx]   = acc;
}

// ---------------- h1 = relu(edge_attr @ nn1_w + nn1_b) -> bf16 ----------------
__global__ void k_edge(const float* __restrict__ ea, const float* __restrict__ w,
                       const float* __restrict__ b) {
    int idx = blockIdx.x * 256 + threadIdx.x;
    if (idx >= NEDGE * H1DIM) return;
    int e = idx >> 7, k = idx & 127;
    const float* er = ea + e * 5;
    float acc = b[k];
#pragma unroll
    for (int f = 0; f < 5; f++) acc = fmaf(er[f], w[f * 128 + k], acc);
    acc = fmaxf(acc, 0.0f);
    g_h1b[idx] = __bfloat16_as_ushort(__float2bfloat16(acc));
}

// ---------------- transpose GRU + LSTM weights (once) ----------------
__global__ void k_prepw(const float* __restrict__ wih, const float* __restrict__ whh,
                        const float* __restrict__ lwih, const float* __restrict__ lwhh) {
    int idx = blockIdx.x * 256 + threadIdx.x;
    if (idx < 64 * 192) {
        int i = idx / 192, j = idx % 192;
        g_wihT[idx] = wih[j * 64 + i];
        g_whhT[idx] = whh[j * 64 + i];
    }
    if (idx < 128 * 256) {
        int i = idx >> 8, j = idx & 255;
        g_lwihT[idx] = lwih[j * 128 + i];
    }
    if (idx < 64 * 256) {
        int i = idx >> 8, j = idx & 255;
        g_lwhhT[idx] = lwhh[j * 64 + i];
    }
}

// ---------------- P[d] = sum_s h1[s->d] (outer) out[s] -> bf16 ----------------
// 128 threads; thread tile 8 k x 8 i; depth-2 software pipeline on the 3 loads
__global__ void __launch_bounds__(128) k_p() {
    int n = blockIdx.x;
    int g = n / NPER, d = n % NPER;
    int t = threadIdx.x;
    int kg = t >> 3, ig = t & 7;        // k = kg*8..+7, i = ig*8..+7
    const float* xbase = g_out + (size_t)g * NPER * 64 + (ig << 3);
    const unsigned short* hbase = g_h1b + (size_t)g * EPG * 128 + (kg << 3);

    unsigned long long acc[8][4];       // [k][i-pair] f32x2
#pragma unroll
    for (int k = 0; k < 8; k++)
#pragma unroll
        for (int c = 0; c < 4; c++) acc[k][c] = 0ULL;

    ulonglong2 xaB[2], xbB[2];
    uint4 hqB[2];
#pragma unroll
    for (int w = 0; w < 2; w++) {
        int s = w + (w >= d);
        int j = (d < s) ? d : d - 1;
        xaB[w] = *(const ulonglong2*)(xbase + s * 64);
        xbB[w] = *(const ulonglong2*)(xbase + s * 64 + 4);
        hqB[w] = *(const uint4*)(hbase + (size_t)(s * 19 + j) * 128);
    }

#pragma unroll 2
    for (int sI = 0; sI < 19; sI++) {
        ulonglong2 xa = xaB[0], xb = xbB[0];
        uint4 hq = hqB[0];
        xaB[0] = xaB[1]; xbB[0] = xbB[1]; hqB[0] = hqB[1];
        if (sI < 17) {
            int sn = (sI + 2) + ((sI + 2) >= d);
            int jn = (d < sn) ? d : d - 1;
            xaB[1] = *(const ulonglong2*)(xbase + sn * 64);
            xbB[1] = *(const ulonglong2*)(xbase + sn * 64 + 4);
            hqB[1] = *(const uint4*)(hbase + (size_t)(sn * 19 + jn) * 128);
        }
        unsigned hw[4] = {hq.x, hq.y, hq.z, hq.w};
#pragma unroll
        for (int p = 0; p < 4; p++) {
            unsigned long long plo, phi;
            PACK2U(plo, hw[p] << 16);
            PACK2U(phi, hw[p] & 0xFFFF0000u);
            int k0 = p << 1, k1 = k0 + 1;
            FMA2(acc[k0][0], plo, xa.x); FMA2(acc[k0][1], plo, xa.y);
            FMA2(acc[k0][2], plo, xb.x); FMA2(acc[k0][3], plo, xb.y);
            FMA2(acc[k1][0], phi, xa.x); FMA2(acc[k1][1], phi, xa.y);
            FMA2(acc[k1][2], phi, xb.x); FMA2(acc[k1][3], phi, xb.y);
        }
    }

    unsigned short* pd = g_Pb + (size_t)n * KK + (ig << 3);
#pragma unroll
    for (int k = 0; k < 8; k++) {
        unsigned o0, o1, o2, o3;
        float lo, hi;
        UNPK2(lo, hi, acc[k][0]); CVTB2(o0, lo, hi);
        UNPK2(lo, hi, acc[k][1]); CVTB2(o1, lo, hi);
        UNPK2(lo, hi, acc[k][2]); CVTB2(o2, lo, hi);
        UNPK2(lo, hi, acc[k][3]); CVTB2(o3, lo, hi);
        *(uint4*)(pd + ((kg << 3) + k) * 64) = make_uint4(o0, o1, o2, o3);
    }
}

// ---------------- k_agg: partial[ks] = Pb[128-row tile] @ T over 256-k slice ----------------
// grid 640 = 20 tiles x 32 K-splits; 128 threads; thread tile 8 rows x 8 cols
__global__ void __launch_bounds__(128, 4) k_agg(const float* __restrict__ nn2w) {
    __shared__ unsigned Tsu[32 * 32];   // 4 KB: [k][col-pair] bf16x2
    int bx = blockIdx.x;
    int tile = bx >> 5, ks = bx & 31;
    int n0 = tile * 128;
    int kbase = ks * 256;
    int t = threadIdx.x;
    int tx = t & 7, ry = t >> 3;        // cols tx*8..+7, rows ry*8..+7
    int r0 = n0 + (ry << 3);

    unsigned long long acc[8][4];       // [row][col-pair] f32x2 {col even, col odd}
#pragma unroll
    for (int r = 0; r < 8; r++)
#pragma unroll
        for (int c = 0; c < 4; c++) acc[r][c] = 0ULL;

    for (int ch = 0; ch < 8; ch++) {
        int kb = kbase + (ch << 5);
        if (ch) __syncthreads();
#pragma unroll
        for (int j = 0; j < 4; j++) {
            int flat = t + j * 128;     // 0..511
            int kk = flat >> 4, o4 = (flat & 15) << 2;
            float4 v = *(const float4*)(nn2w + (size_t)(kb + kk) * 64 + o4);
            unsigned u0, u1;
            CVTB2(u0, v.x, v.y);
            CVTB2(u1, v.z, v.w);
            *(uint2*)(Tsu + (kk << 5) + (o4 >> 1)) = make_uint2(u0, u1);
        }
        __syncthreads();
#pragma unroll
        for (int kq = 0; kq < 4; kq++) {
            uint4 q[8];
#pragma unroll
            for (int r = 0; r < 8; r++)
                q[r] = *(const uint4*)(g_Pb + (size_t)(r0 + r) * KK + kb + (kq << 3));
#pragma unroll
            for (int kk = 0; kk < 8; kk++) {
                uint4 tw = *(const uint4*)(Tsu + (((kq << 3) + kk) << 5) + (tx << 2));
                unsigned long long tp0, tp1, tp2, tp3;
                PACK2UU(tp0, tw.x << 16, tw.x & 0xFFFF0000u);
                PACK2UU(tp1, tw.y << 16, tw.y & 0xFFFF0000u);
                PACK2UU(tp2, tw.z << 16, tw.z & 0xFFFF0000u);
                PACK2UU(tp3, tw.w << 16, tw.w & 0xFFFF0000u);
#pragma unroll
                for (int r = 0; r < 8; r++) {
                    unsigned w = ((const unsigned*)&q[r])[kk >> 1];
                    unsigned f = (kk & 1) ? (w & 0xFFFF0000u) : (w << 16);
                    unsigned long long pd;
                    PACK2U(pd, f);
                    FMA2(acc[r][0], pd, tp0);
                    FMA2(acc[r][1], pd, tp1);
                    FMA2(acc[r][2], pd, tp2);
                    FMA2(acc[r][3], pd, tp3);
                }
            }
        }
    }

    float* gp = g_part + (size_t)ks * (NNODES * DIM) + (size_t)r0 * 64 + (tx << 3);
#pragma unroll
    for (int r = 0; r < 8; r++) {
        ulonglong2 v0, v1;
        v0.x = acc[r][0]; v0.y = acc[r][1];
        v1.x = acc[r][2]; v1.y = acc[r][3];
        *(ulonglong2*)(gp + (size_t)r * 64)     = v0;
        *(ulonglong2*)(gp + (size_t)r * 64 + 4) = v1;
    }
}

// ---------------- fused per-node: Sx via graph-sum; m; GRU -> h,out ----------------
__global__ void k_node(const float* __restrict__ nn2b, const float* __restrict__ rootw,
                       const float* __restrict__ convb,
                       const float* __restrict__ bih, const float* __restrict__ bhh) {
    __shared__ float sx_s[4][64], out_s[4][64], h_s[4][64], m_s[4][64], gpart[4][64];
    int t = threadIdx.x;
    int ln = t >> 6, o = t & 63;
    int n = blockIdx.x * 4 + ln;
    int g = n / NPER;

    out_s[ln][o] = g_out[n * 64 + o];
    h_s[ln][o]   = g_h[n * 64 + o];
    {
        float ps = 0.0f;
        const float* gb = g_out + ((size_t)g * NPER + ln * 5) * 64 + o;
#pragma unroll
        for (int j = 0; j < 5; j++) ps += gb[j * 64];
        gpart[ln][o] = ps;
    }
    __syncthreads();
    sx_s[ln][o] = gpart[0][o] + gpart[1][o] + gpart[2][o] + gpart[3][o] - out_s[ln][o];
    __syncthreads();

    {
        float s = 0.0f;
#pragma unroll
        for (int q = 0; q < KSPLIT; q++) s += g_part[(size_t)q * (NNODES * DIM) + n * 64 + o];
        float acc = 0.0f;
#pragma unroll
        for (int i = 0; i < 64; i++) {
            s   = fmaf(sx_s[ln][i],  nn2b[i * 64 + o], s);
            acc = fmaf(out_s[ln][i], rootw[i * 64 + o], acc);
        }
        m_s[ln][o] = fmaxf(s * (1.0f / 19.0f) + acc + convb[o], 0.0f);
    }
    __syncthreads();

    {
        float gi0 = bih[o], gi1 = bih[o + 64], gi2 = bih[o + 128];
        float gh0 = bhh[o], gh1 = bhh[o + 64], gh2 = bhh[o + 128];
#pragma unroll 8
        for (int i = 0; i < 64; i++) {
            float mi = m_s[ln][i], hi = h_s[ln][i];
            const float* wiT = g_wihT + i * 192 + o;
            const float* whT = g_whhT + i * 192 + o;
            gi0 = fmaf(mi, wiT[0],   gi0);
            gi1 = fmaf(mi, wiT[64],  gi1);
            gi2 = fmaf(mi, wiT[128], gi2);
            gh0 = fmaf(hi, whT[0],   gh0);
            gh1 = fmaf(hi, whT[64],  gh1);
            gh2 = fmaf(hi, whT[128], gh2);
        }
        float r  = sigf(gi0 + gh0);
        float z  = sigf(gi1 + gh1);
        float nn = tanhf(gi2 + r * gh2);
        float h  = (1.0f - z) * nn + z * h_s[ln][o];
        g_h[n * 64 + o]   = h;
        g_out[n * 64 + o] = h;
    }
}

// ---------------- Set2Set (3 steps) + final MLP head, one block per graph ----------------
// LSTM gate GEMVs use transposed weights (coalesced); same summation order
__global__ void k_s2s(const float* __restrict__ bih, const float* __restrict__ bhh,
                      const float* __restrict__ l1w, const float* __restrict__ l1b,
                      const float* __restrict__ l2w, const float* __restrict__ l2b,
                      float* __restrict__ outp) {
    __shared__ float og[NPER * 64];
    __shared__ float qs[128], hl[64], cl[64], gates[256], ev[NPER], av[NPER], red[64];
    __shared__ float ssum;
    int g = blockIdx.x, t = threadIdx.x;               // 128 threads

    for (int u = t; u < NPER * 64; u += 128) og[u] = g_out[g * NPER * 64 + u];
    qs[t] = 0.0f;
    if (t < 64) { hl[t] = 0.0f; cl[t] = 0.0f; }
    __syncthreads();

    for (int step = 0; step < 3; step++) {
#pragma unroll
        for (int jj = 0; jj < 2; jj++) {
            int j = t + jj * 128;
            float acc = bih[j] + bhh[j];
            for (int i = 0; i < 128; i++) acc = fmaf(qs[i], g_lwihT[i * 256 + j], acc);
            for (int i = 0; i < 64; i++)  acc = fmaf(hl[i], g_lwhhT[i * 256 + j], acc);
            gates[j] = acc;
        }
        __syncthreads();
        if (t < 64) {
            float ig = gates[t], fg = gates[64 + t], gg = gates[128 + t], og_ = gates[192 + t];
            float c = sigf(fg) * cl[t] + sigf(ig) * tanhf(gg);
            cl[t] = c;
            hl[t] = sigf(og_) * tanhf(c);
        }
        __syncthreads();
        if (t < NPER) {
            float acc = 0.0f;
            for (int o = 0; o < 64; o++) acc = fmaf(og[t * 64 + o], hl[o], acc);
            ev[t] = acc;
        }
        __syncthreads();
        if (t == 0) {
            float mx = ev[0];
            for (int v = 1; v < NPER; v++) mx = fmaxf(mx, ev[v]);
            float s = 0.0f;
            for (int v = 0; v < NPER; v++) { av[v] = expf(ev[v] - mx); s += av[v]; }
            ssum = s;
        }
        __syncthreads();
        if (t < 64) {
            float acc = 0.0f;
            for (int v = 0; v < NPER; v++) acc = fmaf(av[v], og[v * 64 + t], acc);
            qs[t] = hl[t];
            qs[64 + t] = acc / ssum;
        }
        __syncthreads();
    }

    if (t < 64) {
        float acc = l1b[t];
        for (int i = 0; i < 128; i++) acc = fmaf(qs[i], l1w[i * 64 + t], acc);
        acc = fmaxf(acc, 0.0f);
        red[t] = acc * l2w[t];
    }
    __syncthreads();
    if (t == 0) {
        float y = l2b[0];
        for (int o = 0; o < 64; o++) y += red[o];
        outp[g] = y;
    }
}

// ---------------- host launch ----------------
extern "C" void kernel_launch(void* const* d_in, const int* in_sizes, int n_in,
                              void* d_out, int out_size) {
    const float* x       = (const float*)d_in[0];
    const float* ea      = (const float*)d_in[2];
    const float* lin0_w  = (const float*)d_in[4];
    const float* lin0_b  = (const float*)d_in[5];
    const float* nn1_w   = (const float*)d_in[6];
    const float* nn1_b   = (const float*)d_in[7];
    const float* nn2_w   = (const float*)d_in[8];
    const float* nn2_b   = (const float*)d_in[9];
    const float* root_w  = (const float*)d_in[10];
    const float* conv_b  = (const float*)d_in[11];
    const float* gru_wih = (const float*)d_in[12];
    const float* gru_whh = (const float*)d_in[13];
    const float* gru_bih = (const float*)d_in[14];
    const float* gru_bhh = (const float*)d_in[15];
    const float* lstm_wih = (const float*)d_in[16];
    const float* lstm_whh = (const float*)d_in[17];
    const float* lstm_bih = (const float*)d_in[18];
    const float* lstm_bhh = (const float*)d_in[19];
    const float* lin1_w  = (const float*)d_in[20];
    const float* lin1_b  = (const float*)d_in[21];
    const float* lin2_w  = (const float*)d_in[22];
    const float* lin2_b  = (const float*)d_in[23];
    float* outp = (float*)d_out;

    k_lin0<<<(NNODES * DIM + 255) / 256, 256>>>(x, lin0_w, lin0_b);
    k_edge<<<(NEDGE * H1DIM) / 256, 256>>>(ea, nn1_w, nn1_b);
    k_prepw<<<(128 * 256 + 255) / 256, 256>>>(gru_wih, gru_whh, lstm_wih, lstm_whh);

    for (int it = 0; it < 3; it++) {
        k_p<<<NNODES, 128>>>();
        k_agg<<<640, 128>>>(nn2_w);
        k_node<<<NNODES / 4, 256>>>(nn2_b, root_w, conv_b, gru_bih, gru_bhh);
    }

    k_s2s<<<NGRAPH, 128>>>(lstm_bih, lstm_bhh, lin1_w, lin1_b, lin2_w, lin2_b, outp);
}

// round 17
// speedup vs baseline: 1.1299x; 1.0779x over previous
#include <cuda_runtime.h>
#include <cuda_bf16.h>
#include <math.h>
#include <stdint.h>

// ---------------- problem constants ----------------
#define NGRAPH 128
#define NPER   20
#define NNODES 2560          // 128*20
#define EPG    380           // 20*19
#define NEDGE  48640         // 128*380
#define DIM    64
#define H1DIM  128
#define KK     8192          // H1DIM*DIM
#define KSPLIT 32            // k_agg K-splits (each CTA covers 256 k)

// ---------------- packed f32x2 helpers (sm_100+) ----------------
#define FMA2(acc, a, b) asm("fma.rn.f32x2 %0, %1, %2, %0;" : "+l"(acc) : "l"(a), "l"(b))
#define PACK2(out, f)   asm("mov.b64 %0, {%1, %1};" : "=l"(out) : "f"(f))
#define PACK2U(out, u)  asm("mov.b64 %0, {%1, %1};" : "=l"(out) : "r"(u))
#define PACK2UU(out, a, b) asm("mov.b64 %0, {%1, %2};" : "=l"(out) : "r"(a), "r"(b))
#define UNPK2(lo, hi, p) asm("mov.b64 {%0, %1}, %2;" : "=f"(lo), "=f"(hi) : "l"(p))
#define CVTB2(out, lo, hi) asm("cvt.rn.bf16x2.f32 %0, %1, %2;" : "=r"(out) : "f"(hi), "f"(lo))

// ---------------- scratch (static device globals; no allocation) ----------------
__device__ unsigned short g_h1b[NEDGE * H1DIM];   // 12.5 MB bf16 edge MLP hidden
__device__ unsigned short g_Pb[NNODES * KK];      // 42 MB bf16 outer-product accumulators
__device__ float g_part[KSPLIT * NNODES * DIM];   // 21 MB split-K partials
__device__ float g_out[NNODES * DIM];
__device__ float g_h  [NNODES * DIM];
__device__ float g_wihT[64 * 192];                // GRU weights transposed [i][j]
__device__ float g_whhT[64 * 192];
__device__ float g_lwihT[128 * 256];              // LSTM w_ih transposed [i][j]
__device__ float g_lwhhT[64 * 256];               // LSTM w_hh transposed [i][j]

__device__ __forceinline__ float sigf(float x) { return 1.0f / (1.0f + expf(-x)); }

// ---------------- out = relu(x @ lin0_w + b); h = out ----------------
__global__ void k_lin0(const float* __restrict__ x, const float* __restrict__ w,
                       const float* __restrict__ b) {
    int idx = blockIdx.x * 256 + threadIdx.x;
    if (idx >= NNODES * DIM) return;
    int n = idx >> 6, o = idx & 63;
    const float* xr = x + n * 11;
    float acc = b[o];
#pragma unroll
    for (int f = 0; f < 11; f++) acc = fmaf(xr[f], w[f * 64 + o], acc);
    acc = fmaxf(acc, 0.0f);
    g_out[idx] = acc;
    g_h[idx]   = acc;
}

// ---------------- h1 = relu(edge_attr @ nn1_w + nn1_b) -> bf16 ----------------
__global__ void k_edge(const float* __restrict__ ea, const float* __restrict__ w,
                       const float* __restrict__ b) {
    int idx = blockIdx.x * 256 + threadIdx.x;
    if (idx >= NEDGE * H1DIM) return;
    int e = idx >> 7, k = idx & 127;
    const float* er = ea + e * 5;
    float acc = b[k];
#pragma unroll
    for (int f = 0; f < 5; f++) acc = fmaf(er[f], w[f * 128 + k], acc);
    acc = fmaxf(acc, 0.0f);
    g_h1b[idx] = __bfloat16_as_ushort(__float2bfloat16(acc));
}

// ---------------- transpose GRU + LSTM weights (once) ----------------
__global__ void k_prepw(const float* __restrict__ wih, const float* __restrict__ whh,
                        const float* __restrict__ lwih, const float* __restrict__ lwhh) {
    int idx = blockIdx.x * 256 + threadIdx.x;
    if (idx < 64 * 192) {
        int i = idx / 192, j = idx % 192;
        g_wihT[idx] = wih[j * 64 + i];
        g_whhT[idx] = whh[j * 64 + i];
    }
    if (idx < 128 * 256) {
        int i = idx >> 8, j = idx & 255;
        g_lwihT[idx] = lwih[j * 128 + i];
    }
    if (idx < 64 * 256) {
        int i = idx >> 8, j = idx & 255;
        g_lwhhT[idx] = lwhh[j * 64 + i];
    }
}

// ---------------- P[d] = sum_s h1[s->d] (outer) out[s] -> bf16 ----------------
// 128 threads; thread tile 8 k x 8 i; depth-1 software pipeline (measured best)
__global__ void __launch_bounds__(128) k_p() {
    int n = blockIdx.x;
    int g = n / NPER, d = n % NPER;
    int t = threadIdx.x;
    int kg = t >> 3, ig = t & 7;        // k = kg*8..+7, i = ig*8..+7
    const float* xbase = g_out + (size_t)g * NPER * 64 + (ig << 3);
    const unsigned short* hbase = g_h1b + (size_t)g * EPG * 128 + (kg << 3);

    unsigned long long acc[8][4];       // [k][i-pair] f32x2
#pragma unroll
    for (int k = 0; k < 8; k++)
#pragma unroll
        for (int c = 0; c < 4; c++) acc[k][c] = 0ULL;

    int s0 = 0 + (0 >= d);
    int j0 = (d < s0) ? d : d - 1;
    ulonglong2 xa = *(const ulonglong2*)(xbase + s0 * 64);
    ulonglong2 xb = *(const ulonglong2*)(xbase + s0 * 64 + 4);
    uint4 hq = *(const uint4*)(hbase + (size_t)(s0 * 19 + j0) * 128);

    for (int sI = 0; sI < 19; sI++) {
        ulonglong2 xa2, xb2;
        uint4 hq2;
        if (sI < 18) {
            int sn = (sI + 1) + ((sI + 1) >= d);
            int jn = (d < sn) ? d : d - 1;
            xa2 = *(const ulonglong2*)(xbase + sn * 64);
            xb2 = *(const ulonglong2*)(xbase + sn * 64 + 4);
            hq2 = *(const uint4*)(hbase + (size_t)(sn * 19 + jn) * 128);
        }
        unsigned hw[4] = {hq.x, hq.y, hq.z, hq.w};
#pragma unroll
        for (int p = 0; p < 4; p++) {
            unsigned long long plo, phi;
            PACK2U(plo, hw[p] << 16);
            PACK2U(phi, hw[p] & 0xFFFF0000u);
            int k0 = p << 1, k1 = k0 + 1;
            FMA2(acc[k0][0], plo, xa.x); FMA2(acc[k0][1], plo, xa.y);
            FMA2(acc[k0][2], plo, xb.x); FMA2(acc[k0][3], plo, xb.y);
            FMA2(acc[k1][0], phi, xa.x); FMA2(acc[k1][1], phi, xa.y);
            FMA2(acc[k1][2], phi, xb.x); FMA2(acc[k1][3], phi, xb.y);
        }
        xa = xa2; xb = xb2; hq = hq2;
    }

    unsigned short* pd = g_Pb + (size_t)n * KK + (ig << 3);
#pragma unroll
    for (int k = 0; k < 8; k++) {
        unsigned o0, o1, o2, o3;
        float lo, hi;
        UNPK2(lo, hi, acc[k][0]); CVTB2(o0, lo, hi);
        UNPK2(lo, hi, acc[k][1]); CVTB2(o1, lo, hi);
        UNPK2(lo, hi, acc[k][2]); CVTB2(o2, lo, hi);
        UNPK2(lo, hi, acc[k][3]); CVTB2(o3, lo, hi);
        *(uint4*)(pd + ((kg << 3) + k) * 64) = make_uint4(o0, o1, o2, o3);
    }
}

// ---------------- k_agg: partial[ks] = Pb[128-row tile] @ T over 256-k slice ----------------
// grid 640 = 20 tiles x 32 K-splits; 128 threads; thread tile 8 rows x 8 cols
__global__ void __launch_bounds__(128, 4) k_agg(const float* __restrict__ nn2w) {
    __shared__ unsigned Tsu[32 * 32];   // 4 KB: [k][col-pair] bf16x2
    int bx = blockIdx.x;
    int tile = bx >> 5, ks = bx & 31;
    int n0 = tile * 128;
    int kbase = ks * 256;
    int t = threadIdx.x;
    int tx = t & 7, ry = t >> 3;        // cols tx*8..+7, rows ry*8..+7
    int r0 = n0 + (ry << 3);

    unsigned long long acc[8][4];       // [row][col-pair] f32x2 {col even, col odd}
#pragma unroll
    for (int r = 0; r < 8; r++)
#pragma unroll
        for (int c = 0; c < 4; c++) acc[r][c] = 0ULL;

    for (int ch = 0; ch < 8; ch++) {
        int kb = kbase + (ch << 5);
        if (ch) __syncthreads();
#pragma unroll
        for (int j = 0; j < 4; j++) {
            int flat = t + j * 128;     // 0..511
            int kk = flat >> 4, o4 = (flat & 15) << 2;
            float4 v = *(const float4*)(nn2w + (size_t)(kb + kk) * 64 + o4);
            unsigned u0, u1;
            CVTB2(u0, v.x, v.y);
            CVTB2(u1, v.z, v.w);
            *(uint2*)(Tsu + (kk << 5) + (o4 >> 1)) = make_uint2(u0, u1);
        }
        __syncthreads();
#pragma unroll
        for (int kq = 0; kq < 4; kq++) {
            uint4 q[8];
#pragma unroll
            for (int r = 0; r < 8; r++)
                q[r] = *(const uint4*)(g_Pb + (size_t)(r0 + r) * KK + kb + (kq << 3));
#pragma unroll
            for (int kk = 0; kk < 8; kk++) {
                uint4 tw = *(const uint4*)(Tsu + (((kq << 3) + kk) << 5) + (tx << 2));
                unsigned long long tp0, tp1, tp2, tp3;
                PACK2UU(tp0, tw.x << 16, tw.x & 0xFFFF0000u);
                PACK2UU(tp1, tw.y << 16, tw.y & 0xFFFF0000u);
                PACK2UU(tp2, tw.z << 16, tw.z & 0xFFFF0000u);
                PACK2UU(tp3, tw.w << 16, tw.w & 0xFFFF0000u);
#pragma unroll
                for (int r = 0; r < 8; r++) {
                    unsigned w = ((const unsigned*)&q[r])[kk >> 1];
                    unsigned f = (kk & 1) ? (w & 0xFFFF0000u) : (w << 16);
                    unsigned long long pd;
                    PACK2U(pd, f);
                    FMA2(acc[r][0], pd, tp0);
                    FMA2(acc[r][1], pd, tp1);
                    FMA2(acc[r][2], pd, tp2);
                    FMA2(acc[r][3], pd, tp3);
                }
            }
        }
    }

    float* gp = g_part + (size_t)ks * (NNODES * DIM) + (size_t)r0 * 64 + (tx << 3);
#pragma unroll
    for (int r = 0; r < 8; r++) {
        ulonglong2 v0, v1;
        v0.x = acc[r][0]; v0.y = acc[r][1];
        v1.x = acc[r][2]; v1.y = acc[r][3];
        *(ulonglong2*)(gp + (size_t)r * 64)     = v0;
        *(ulonglong2*)(gp + (size_t)r * 64 + 4) = v1;
    }
}

// ---------------- fused per-node: Sx via graph-sum; m; GRU -> h,out ----------------
__global__ void k_node(const float* __restrict__ nn2b, const float* __restrict__ rootw,
                       const float* __restrict__ convb,
                       const float* __restrict__ bih, const float* __restrict__ bhh) {
    __shared__ float sx_s[4][64], out_s[4][64], h_s[4][64], m_s[4][64], gpart[4][64];
    int t = threadIdx.x;
    int ln = t >> 6, o = t & 63;
    int n = blockIdx.x * 4 + ln;
    int g = n / NPER;

    out_s[ln][o] = g_out[n * 64 + o];
    h_s[ln][o]   = g_h[n * 64 + o];
    {
        float ps = 0.0f;
        const float* gb = g_out + ((size_t)g * NPER + ln * 5) * 64 + o;
#pragma unroll
        for (int j = 0; j < 5; j++) ps += gb[j * 64];
        gpart[ln][o] = ps;
    }
    __syncthreads();
    sx_s[ln][o] = gpart[0][o] + gpart[1][o] + gpart[2][o] + gpart[3][o] - out_s[ln][o];
    __syncthreads();

    {
        float s = 0.0f;
#pragma unroll
        for (int q = 0; q < KSPLIT; q++) s += g_part[(size_t)q * (NNODES * DIM) + n * 64 + o];
        float acc = 0.0f;
#pragma unroll
        for (int i = 0; i < 64; i++) {
            s   = fmaf(sx_s[ln][i],  nn2b[i * 64 + o], s);
            acc = fmaf(out_s[ln][i], rootw[i * 64 + o], acc);
        }
        m_s[ln][o] = fmaxf(s * (1.0f / 19.0f) + acc + convb[o], 0.0f);
    }
    __syncthreads();

    {
        float gi0 = bih[o], gi1 = bih[o + 64], gi2 = bih[o + 128];
        float gh0 = bhh[o], gh1 = bhh[o + 64], gh2 = bhh[o + 128];
#pragma unroll 8
        for (int i = 0; i < 64; i++) {
            float mi = m_s[ln][i], hi = h_s[ln][i];
            const float* wiT = g_wihT + i * 192 + o;
            const float* whT = g_whhT + i * 192 + o;
            gi0 = fmaf(mi, wiT[0],   gi0);
            gi1 = fmaf(mi, wiT[64],  gi1);
            gi2 = fmaf(mi, wiT[128], gi2);
            gh0 = fmaf(hi, whT[0],   gh0);
            gh1 = fmaf(hi, whT[64],  gh1);
            gh2 = fmaf(hi, whT[128], gh2);
        }
        float r  = sigf(gi0 + gh0);
        float z  = sigf(gi1 + gh1);
        float nn = tanhf(gi2 + r * gh2);
        float h  = (1.0f - z) * nn + z * h_s[ln][o];
        g_h[n * 64 + o]   = h;
        g_out[n * 64 + o] = h;
    }
}

// ---------------- Set2Set (3 steps) + final MLP head, one block per graph ----------------
// LSTM gate GEMVs use transposed weights (coalesced); same summation order
__global__ void k_s2s(const float* __restrict__ bih, const float* __restrict__ bhh,
                      const float* __restrict__ l1w, const float* __restrict__ l1b,
                      const float* __restrict__ l2w, const float* __restrict__ l2b,
                      float* __restrict__ outp) {
    __shared__ float og[NPER * 64];
    __shared__ float qs[128], hl[64], cl[64], gates[256], ev[NPER], av[NPER], red[64];
    __shared__ float ssum;
    int g = blockIdx.x, t = threadIdx.x;               // 128 threads

    for (int u = t; u < NPER * 64; u += 128) og[u] = g_out[g * NPER * 64 + u];
    qs[t] = 0.0f;
    if (t < 64) { hl[t] = 0.0f; cl[t] = 0.0f; }
    __syncthreads();

    for (int step = 0; step < 3; step++) {
#pragma unroll
        for (int jj = 0; jj < 2; jj++) {
            int j = t + jj * 128;
            float acc = bih[j] + bhh[j];
            for (int i = 0; i < 128; i++) acc = fmaf(qs[i], g_lwihT[i * 256 + j], acc);
            for (int i = 0; i < 64; i++)  acc = fmaf(hl[i], g_lwhhT[i * 256 + j], acc);
            gates[j] = acc;
        }
        __syncthreads();
        if (t < 64) {
            float ig = gates[t], fg = gates[64 + t], gg = gates[128 + t], og_ = gates[192 + t];
            float c = sigf(fg) * cl[t] + sigf(ig) * tanhf(gg);
            cl[t] = c;
            hl[t] = sigf(og_) * tanhf(c);
        }
        __syncthreads();
        if (t < NPER) {
            float acc = 0.0f;
            for (int o = 0; o < 64; o++) acc = fmaf(og[t * 64 + o], hl[o], acc);
            ev[t] = acc;
        }
        __syncthreads();
        if (t == 0) {
            float mx = ev[0];
            for (int v = 1; v < NPER; v++) mx = fmaxf(mx, ev[v]);
            float s = 0.0f;
            for (int v = 0; v < NPER; v++) { av[v] = expf(ev[v] - mx); s += av[v]; }
            ssum = s;
        }
        __syncthreads();
        if (t < 64) {
            float acc = 0.0f;
            for (int v = 0; v < NPER; v++) acc = fmaf(av[v], og[v * 64 + t], acc);
            qs[t] = hl[t];
            qs[64 + t] = acc / ssum;
        }
        __syncthreads();
    }

    if (t < 64) {
        float acc = l1b[t];
        for (int i = 0; i < 128; i++) acc = fmaf(qs[i], l1w[i * 64 + t], acc);
        acc = fmaxf(acc, 0.0f);
        red[t] = acc * l2w[t];
    }
    __syncthreads();
    if (t == 0) {
        float y = l2b[0];
        for (int o = 0; o < 64; o++) y += red[o];
        outp[g] = y;
    }
}

// ---------------- host launch ----------------
extern "C" void kernel_launch(void* const* d_in, const int* in_sizes, int n_in,
                              void* d_out, int out_size) {
    const float* x       = (const float*)d_in[0];
    const float* ea      = (const float*)d_in[2];
    const float* lin0_w  = (const float*)d_in[4];
    const float* lin0_b  = (const float*)d_in[5];
    const float* nn1_w   = (const float*)d_in[6];
    const float* nn1_b   = (const float*)d_in[7];
    const float* nn2_w   = (const float*)d_in[8];
    const float* nn2_b   = (const float*)d_in[9];
    const float* root_w  = (const float*)d_in[10];
    const float* conv_b  = (const float*)d_in[11];
    const float* gru_wih = (const float*)d_in[12];
    const float* gru_whh = (const float*)d_in[13];
    const float* gru_bih = (const float*)d_in[14];
    const float* gru_bhh = (const float*)d_in[15];
    const float* lstm_wih = (const float*)d_in[16];
    const float* lstm_whh = (const float*)d_in[17];
    const float* lstm_bih = (const float*)d_in[18];
    const float* lstm_bhh = (const float*)d_in[19];
    const float* lin1_w  = (const float*)d_in[20];
    const float* lin1_b  = (const float*)d_in[21];
    const float* lin2_w  = (const float*)d_in[22];
    const float* lin2_b  = (const float*)d_in[23];
    float* outp = (float*)d_out;

    k_lin0<<<(NNODES * DIM + 255) / 256, 256>>>(x, lin0_w, lin0_b);
    k_edge<<<(NEDGE * H1DIM) / 256, 256>>>(ea, nn1_w, nn1_b);
    k_prepw<<<(128 * 256 + 255) / 256, 256>>>(gru_wih, gru_whh, lstm_wih, lstm_whh);

    for (int it = 0; it < 3; it++) {
        k_p<<<NNODES, 128>>>();
        k_agg<<<640, 128>>>(nn2_w);
        k_node<<<NNODES / 4, 256>>>(nn2_b, root_w, conv_b, gru_bih, gru_bhh);
    }

    k_s2s<<<NGRAPH, 128>>>(lstm_bih, lstm_bhh, lin1_w, lin1_b, lin2_w, lin2_b, outp);
}